// round 2
// baseline (speedup 1.0000x reference)
#include <cuda_runtime.h>

#define SQ   2048
#define DM   1024
#define NH   16
#define DH   64
#define BT   4
#define ROWS (BT * SQ)   // 8192

// Scratch (device globals — no allocation allowed)
__device__ float g_q[(size_t)BT * NH * SQ * DH];
__device__ float g_k[(size_t)BT * NH * SQ * DH];
__device__ float g_v[(size_t)BT * NH * SQ * DH];
__device__ float g_attn[(size_t)ROWS * DM];

// ---------------------------------------------------------------------------
// SGEMM: C(8192 x 1024) = A(8192 x 1024) @ W + bias
// MODE 0 (QKV): W is (H, DM, DH) -> logical col n = h*64+d ; C written to
//               g_q/g_k/g_v (selected by DST) in [b][h][s][d] layout.
// MODE 1 (out proj): W is row-major (1024,1024); A = g_attn; C = param (row-major).
// 128x128x8 tile, 256 threads, 8x8 microtile, register prefetch pipeline.
// ---------------------------------------------------------------------------
template <int MODE, int DST>
__global__ __launch_bounds__(256) void gemm_kernel(
    const float* __restrict__ A,
    const float* __restrict__ W,
    const float* __restrict__ bias,
    float* __restrict__ Cparam)
{
    __shared__ float As[8][128];   // k-major (transposed A tile)
    __shared__ float Bs[8][128];

    const int tid = threadIdx.x;
    const int tx = tid & 15;       // column group
    const int ty = tid >> 4;       // row group
    const int n0 = blockIdx.x * 128;
    const int m0 = blockIdx.y * 128;

    // loaders
    const int lrow = tid >> 1;          // 0..127
    const int lk   = (tid & 1) << 2;    // 0 or 4
    const int bk   = tid >> 5;          // 0..7
    const int bn   = (tid & 31) << 2;   // 0..124

    const float* Ap = (MODE == 0 ? A : g_attn) + (size_t)(m0 + lrow) * DM + lk;
    const float* Wp;
    if (MODE == 0) {
        const int n = n0 + bn;
        Wp = W + (size_t)(n >> 6) * (DM * DH) + (size_t)bk * DH + (n & 63);
    } else {
        Wp = W + (size_t)bk * DM + n0 + bn;
    }

    float acc[8][8];
#pragma unroll
    for (int i = 0; i < 8; i++)
#pragma unroll
        for (int j = 0; j < 8; j++) acc[i][j] = 0.f;

    // prefetch first tile
    float4 av = *(const float4*)Ap;
    float4 bv = *(const float4*)Wp;

    for (int k0 = 0; k0 < DM; k0 += 8) {
        As[lk + 0][lrow] = av.x;
        As[lk + 1][lrow] = av.y;
        As[lk + 2][lrow] = av.z;
        As[lk + 3][lrow] = av.w;
        *(float4*)&Bs[bk][bn] = bv;
        __syncthreads();

        if (k0 + 8 < DM) {   // prefetch next tile during compute
            av = *(const float4*)(Ap + k0 + 8);
            bv = *(const float4*)(Wp + (MODE == 0 ? (size_t)(k0 + 8) * DH
                                                  : (size_t)(k0 + 8) * DM));
        }

#pragma unroll
        for (int k = 0; k < 8; k++) {
            float a[8], b[8];
            *(float4*)&a[0] = *(const float4*)&As[k][ty << 2];
            *(float4*)&a[4] = *(const float4*)&As[k][(ty << 2) + 64];
            *(float4*)&b[0] = *(const float4*)&Bs[k][tx << 2];
            *(float4*)&b[4] = *(const float4*)&Bs[k][(tx << 2) + 64];
#pragma unroll
            for (int i = 0; i < 8; i++)
#pragma unroll
                for (int j = 0; j < 8; j++)
                    acc[i][j] += a[i] * b[j];
        }
        __syncthreads();
    }

    // epilogue
    float* Cq = (DST == 0) ? g_q : (DST == 1) ? g_k : g_v;
#pragma unroll
    for (int i = 0; i < 8; i++) {
        const int row = m0 + (ty << 2) + (i & 3) + ((i >> 2) << 6);
#pragma unroll
        for (int jq = 0; jq < 2; jq++) {
            const int col = n0 + (tx << 2) + (jq << 6);
            float4 v;
            v.x = acc[i][jq * 4 + 0] + bias[col + 0];
            v.y = acc[i][jq * 4 + 1] + bias[col + 1];
            v.z = acc[i][jq * 4 + 2] + bias[col + 2];
            v.w = acc[i][jq * 4 + 3] + bias[col + 3];
            if (MODE == 0) {
                const int bidx = row >> 11;       // /2048
                const int s    = row & 2047;
                const int h    = col >> 6;
                const int d    = col & 63;        // multiple of 4, <64
                *(float4*)&Cq[(((size_t)(bidx * NH + h)) * SQ + s) * DH + d] = v;
            } else {
                *(float4*)&Cparam[(size_t)row * DM + col] = v;
            }
        }
    }
}

// ---------------------------------------------------------------------------
// Flash attention (fp32, causal). One block = (q-tile of 64 rows, head, batch).
// 128 threads; cyclic microtile: thread(rg=tid/8, cg=tid&7) owns rows
// {rg+16*ii} and cols {cg+8*jj}. Q/K/P tiles XOR-granule-swizzled in smem
// (conflict-free float4 reads); V tile plain (conflict-free scalar reads).
// P reuses the K buffer -> 48KB static smem total.
// ---------------------------------------------------------------------------
__global__ __launch_bounds__(128) void attn_kernel()
{
    __shared__ float Qs[64 * 64];
    __shared__ float KPs[64 * 64];
    __shared__ float Vs[64 * 64];

    const int qt  = (SQ / 64 - 1) - (int)blockIdx.x;   // heavy tiles first
    const int h   = blockIdx.y;
    const int b   = blockIdx.z;
    const int tid = threadIdx.x;
    const int cg  = tid & 7;
    const int rg  = tid >> 3;        // 0..15
    const int key = rg & 7;          // swizzle key for this thread's rows

    const size_t base = (size_t)(b * NH + h) * SQ * DH;
    const float* Qg = g_q + base + (size_t)qt * 64 * DH;
    const float* Kg = g_k + base;
    const float* Vg = g_v + base;

    // load Q tile (swizzled)
#pragma unroll
    for (int i = 0; i < 8; i++) {
        const int f   = tid + (i << 7);
        const int row = f >> 4;
        const int c4  = f & 15;
        float4 v = *(const float4*)(Qg + row * DH + (c4 << 2));
        *(float4*)&Qs[row * 64 + ((c4 ^ (row & 7)) << 2)] = v;
    }

    float m_i[4], l_i[4], acc[4][8];
#pragma unroll
    for (int ii = 0; ii < 4; ii++) {
        m_i[ii] = -1e30f;
        l_i[ii] = 0.f;
#pragma unroll
        for (int mm = 0; mm < 8; mm++) acc[ii][mm] = 0.f;
    }

    for (int kt = 0; kt <= qt; kt++) {
        const float* Kt = Kg + (size_t)kt * 64 * DH;
        const float* Vt = Vg + (size_t)kt * 64 * DH;
        // load K (swizzled) + V (plain)
#pragma unroll
        for (int i = 0; i < 8; i++) {
            const int f   = tid + (i << 7);
            const int row = f >> 4;
            const int c4  = f & 15;
            float4 kv = *(const float4*)(Kt + row * DH + (c4 << 2));
            *(float4*)&KPs[row * 64 + ((c4 ^ (row & 7)) << 2)] = kv;
            float4 vv = *(const float4*)(Vt + row * DH + (c4 << 2));
            *(float4*)&Vs[row * 64 + (c4 << 2)] = vv;
        }
        __syncthreads();

        // S = Q @ K^T  (contract d, vectorized by 4)
        float s[4][8];
#pragma unroll
        for (int ii = 0; ii < 4; ii++)
#pragma unroll
            for (int jj = 0; jj < 8; jj++) s[ii][jj] = 0.f;

#pragma unroll
        for (int d4 = 0; d4 < 16; d4++) {
            float4 qf[4], kf[8];
#pragma unroll
            for (int ii = 0; ii < 4; ii++)
                qf[ii] = *(const float4*)&Qs[(rg + (ii << 4)) * 64 + ((d4 ^ key) << 2)];
#pragma unroll
            for (int jj = 0; jj < 8; jj++)
                kf[jj] = *(const float4*)&KPs[(cg + (jj << 3)) * 64 + ((d4 ^ cg) << 2)];
#pragma unroll
            for (int ii = 0; ii < 4; ii++)
#pragma unroll
                for (int jj = 0; jj < 8; jj++)
                    s[ii][jj] += qf[ii].x * kf[jj].x + qf[ii].y * kf[jj].y +
                                 qf[ii].z * kf[jj].z + qf[ii].w * kf[jj].w;
        }

        // online softmax (stats replicated across the 8 cg lanes of each rg)
        float fs[4];
#pragma unroll
        for (int ii = 0; ii < 4; ii++) {
            float tm = -1e30f;
#pragma unroll
            for (int jj = 0; jj < 8; jj++) {
                float v = s[ii][jj] * 0.125f;                      // 1/sqrt(64)
                if (kt == qt && (cg + (jj << 3)) > (rg + (ii << 4)))
                    v = -100000.0f;                                // NEG_MASK
                s[ii][jj] = v;
                tm = fmaxf(tm, v);
            }
            tm = fmaxf(tm, __shfl_xor_sync(0xffffffffu, tm, 1));
            tm = fmaxf(tm, __shfl_xor_sync(0xffffffffu, tm, 2));
            tm = fmaxf(tm, __shfl_xor_sync(0xffffffffu, tm, 4));
            const float mn = fmaxf(m_i[ii], tm);
            const float f  = __expf(m_i[ii] - mn);
            m_i[ii] = mn;
            fs[ii]  = f;
            float rs = 0.f;
#pragma unroll
            for (int jj = 0; jj < 8; jj++) {
                const float p = __expf(s[ii][jj] - mn);
                s[ii][jj] = p;
                rs += p;
            }
            rs += __shfl_xor_sync(0xffffffffu, rs, 1);
            rs += __shfl_xor_sync(0xffffffffu, rs, 2);
            rs += __shfl_xor_sync(0xffffffffu, rs, 4);
            l_i[ii] = l_i[ii] * f + rs;
#pragma unroll
            for (int mm = 0; mm < 8; mm++) acc[ii][mm] *= fs[ii];
        }
        __syncthreads();   // all K reads done before P overwrites the buffer

        // store P (swizzled, same layout as K)
#pragma unroll
        for (int ii = 0; ii < 4; ii++) {
            const int i = rg + (ii << 4);
#pragma unroll
            for (int jj = 0; jj < 8; jj++) {
                const int j = cg + (jj << 3);
                KPs[i * 64 + (((j >> 2) ^ key) << 2) + (j & 3)] = s[ii][jj];
            }
        }
        __syncthreads();

        // O += P @ V  (contract j, vectorized by 4 on P)
#pragma unroll
        for (int j4 = 0; j4 < 16; j4++) {
            float4 pf[4];
#pragma unroll
            for (int ii = 0; ii < 4; ii++)
                pf[ii] = *(const float4*)&KPs[(rg + (ii << 4)) * 64 + ((j4 ^ key) << 2)];
#pragma unroll
            for (int c = 0; c < 4; c++) {
                const int j = (j4 << 2) + c;
                float vv[8];
#pragma unroll
                for (int mm = 0; mm < 8; mm++)
                    vv[mm] = Vs[j * 64 + cg + (mm << 3)];
#pragma unroll
                for (int ii = 0; ii < 4; ii++) {
                    const float p = (c == 0) ? pf[ii].x : (c == 1) ? pf[ii].y
                                  : (c == 2) ? pf[ii].z : pf[ii].w;
#pragma unroll
                    for (int mm = 0; mm < 8; mm++)
                        acc[ii][mm] += p * vv[mm];
                }
            }
        }
        __syncthreads();   // PV reads done before next tile's K/V overwrite
    }

    // normalize + write to g_attn in [b*s][h*64+d] layout (for out-proj GEMM)
#pragma unroll
    for (int ii = 0; ii < 4; ii++) {
        const float inv = 1.0f / l_i[ii];
        const int row   = b * SQ + qt * 64 + rg + (ii << 4);
#pragma unroll
        for (int mm = 0; mm < 8; mm++)
            g_attn[(size_t)row * DM + h * DH + cg + (mm << 3)] = acc[ii][mm] * inv;
    }
}

// ---------------------------------------------------------------------------
extern "C" void kernel_launch(void* const* d_in, const int* in_sizes, int n_in,
                              void* d_out, int out_size)
{
    const float* x  = (const float*)d_in[0];
    const float* Qw = (const float*)d_in[1];
    const float* Qb = (const float*)d_in[2];
    const float* Kw = (const float*)d_in[3];
    const float* Kb = (const float*)d_in[4];
    const float* Vw = (const float*)d_in[5];
    const float* Vb = (const float*)d_in[6];
    const float* Ow = (const float*)d_in[7];
    const float* Ob = (const float*)d_in[8];
    float* out = (float*)d_out;

    dim3 gp(DM / 128, ROWS / 128);   // (8, 64)
    gemm_kernel<0, 0><<<gp, 256>>>(x, Qw, Qb, nullptr);
    gemm_kernel<0, 1><<<gp, 256>>>(x, Kw, Kb, nullptr);
    gemm_kernel<0, 2><<<gp, 256>>>(x, Vw, Vb, nullptr);
    attn_kernel<<<dim3(SQ / 64, NH, BT), 128>>>();
    gemm_kernel<1, 0><<<gp, 256>>>(nullptr, Ow, Ob, out);
}

// round 7
// speedup vs baseline: 1.2015x; 1.2015x over previous
#include <cuda_runtime.h>
#include <cuda_bf16.h>
#include <stdint.h>

#define SQ   2048
#define DM   1024
#define NH   16
#define DH   64
#define BT   4
#define ROWS (BT * SQ)   // 8192

// ---------------- scratch (device globals; no allocation allowed) ----------
__device__ float g_q[(size_t)ROWS * DM];
__device__ float g_k[(size_t)ROWS * DM];
__device__ float g_v[(size_t)ROWS * DM];
__device__ __nv_bfloat16 g_xhi[(size_t)ROWS * DM];
__device__ __nv_bfloat16 g_xlo[(size_t)ROWS * DM];
__device__ __nv_bfloat16 g_ahi[(size_t)ROWS * DM];
__device__ __nv_bfloat16 g_alo[(size_t)ROWS * DM];
__device__ __nv_bfloat16 g_wthi[(size_t)DM * DM];
__device__ __nv_bfloat16 g_wtlo[(size_t)DM * DM];

// ---------------- PTX helpers (sm_103-safe: no tcgen05) --------------------
__device__ __forceinline__ uint32_t s2u(const void* p) {
    uint32_t a;
    asm("{ .reg .u64 t; cvta.to.shared.u64 t, %1; cvt.u32.u64 %0, t; }"
        : "=r"(a) : "l"(p));
    return a;
}
__device__ __forceinline__ void cpa16(uint32_t dst, const void* src) {
    asm volatile("cp.async.cg.shared.global [%0], [%1], 16;"
                 :: "r"(dst), "l"(src));
}
__device__ __forceinline__ void cpa_commit() {
    asm volatile("cp.async.commit_group;" ::: "memory");
}
template <int N>
__device__ __forceinline__ void cpa_wait() {
    asm volatile("cp.async.wait_group %0;" :: "n"(N) : "memory");
}
__device__ __forceinline__ void ldm4(uint32_t* r, uint32_t addr) {
    asm volatile("ldmatrix.sync.aligned.m8n8.x4.shared.b16 {%0,%1,%2,%3}, [%4];"
                 : "=r"(r[0]), "=r"(r[1]), "=r"(r[2]), "=r"(r[3]) : "r"(addr));
}
__device__ __forceinline__ void mma16816(float* c, const uint32_t* a,
                                         uint32_t b0, uint32_t b1) {
    asm volatile("mma.sync.aligned.m16n8k16.row.col.f32.bf16.bf16.f32 "
                 "{%0,%1,%2,%3}, {%4,%5,%6,%7}, {%8,%9}, {%0,%1,%2,%3};"
                 : "+f"(c[0]), "+f"(c[1]), "+f"(c[2]), "+f"(c[3])
                 : "r"(a[0]), "r"(a[1]), "r"(a[2]), "r"(a[3]),
                   "r"(b0), "r"(b1));
}
__device__ __forceinline__ uint32_t sw128(uint32_t off) {
    return off ^ ((off >> 3) & 0x70);
}

// ---------------- conversion kernels ---------------------------------------
__global__ void cvt_split(const float* __restrict__ s,
                          __nv_bfloat16* __restrict__ hi,
                          __nv_bfloat16* __restrict__ lo) {
    int i = blockIdx.x * blockDim.x + threadIdx.x;
    float4 v = ((const float4*)s)[i];
    __nv_bfloat16 h0 = __float2bfloat16(v.x), h1 = __float2bfloat16(v.y);
    __nv_bfloat16 h2 = __float2bfloat16(v.z), h3 = __float2bfloat16(v.w);
    __nv_bfloat16 l0 = __float2bfloat16(v.x - __bfloat162float(h0));
    __nv_bfloat16 l1 = __float2bfloat16(v.y - __bfloat162float(h1));
    __nv_bfloat16 l2 = __float2bfloat16(v.z - __bfloat162float(h2));
    __nv_bfloat16 l3 = __float2bfloat16(v.w - __bfloat162float(h3));
    ((__nv_bfloat162*)hi)[2 * i]     = __nv_bfloat162(h0, h1);
    ((__nv_bfloat162*)hi)[2 * i + 1] = __nv_bfloat162(h2, h3);
    ((__nv_bfloat162*)lo)[2 * i]     = __nv_bfloat162(l0, l1);
    ((__nv_bfloat162*)lo)[2 * i + 1] = __nv_bfloat162(l2, l3);
}

// Transpose + split weight into g_wthi/g_wtlo as [n][k] (k contiguous).
// QKV=1: W is (H, DM, DH), col n = h*64+d.  QKV=0: W flat is [k][n] (O_w).
template <int QKV>
__global__ void cvt_wT(const float* __restrict__ W) {
    int id = blockIdx.x * blockDim.x + threadIdx.x;  // id = n*1024 + k
    int k = id & (DM - 1);
    int n = id >> 10;
    float v;
    if (QKV) v = W[(size_t)(n >> 6) * (DM * DH) + (size_t)k * DH + (n & 63)];
    else     v = W[(size_t)k * DM + n];
    __nv_bfloat16 h = __float2bfloat16(v);
    g_wthi[id] = h;
    g_wtlo[id] = __float2bfloat16(v - __bfloat162float(h));
}

// ---------------- HMMA GEMM ------------------------------------------------
// C(8192 x 1024) = A @ W^T + bias,  bf16-split 3-pass, fp32 accum.
// 128x128 tile, 256 thr (8 warps, 4x2), warp tile 32x64, mma.sync m16n8k16.
// K-chunk 64, 2-stage cp.async pipeline, SW128-swizzled smem.
// MODE 0: C -> g_q/g_k/g_v (DST) in [b][h][s][d].  MODE 1: C -> Cout row-major.
#define STAGE_BYTES 65536     // 4 tensors x 128 rows x 128B
#define SMEMSZ      (2 * STAGE_BYTES)

template <int MODE, int DST>
__global__ __launch_bounds__(256) void tc_gemm(
    const __nv_bfloat16* __restrict__ Ahi,
    const __nv_bfloat16* __restrict__ Alo,
    const float* __restrict__ bias,
    float* __restrict__ Cout)
{
    extern __shared__ char smem[];
    const uint32_t sb = s2u(smem);
    const int tid  = threadIdx.x;
    const int lane = tid & 31;
    const int wid  = tid >> 5;
    const int mw   = wid & 3;            // 4 m-groups of 32 rows
    const int nw   = wid >> 2;           // 2 n-groups of 64 cols
    const int n0 = blockIdx.x * 128;
    const int m0 = blockIdx.y * 128;

    auto load_chunk = [&](int c, int s) {
        const uint32_t ab = sb + s * STAGE_BYTES;
        const int row = tid >> 1;
        const size_t arow = (size_t)(m0 + row) * DM;
        const size_t brow = (size_t)(n0 + row) * DM;
        const size_t kof = (size_t)c * 64;
#pragma unroll
        for (int i = 0; i < 4; i++) {
            const int seg = ((tid & 1) << 2) + i;
            const uint32_t sw = sw128(row * 128 + seg * 16);
            const size_t ka = kof + seg * 8;
            cpa16(ab + sw,         Ahi    + arow + ka);
            cpa16(ab + 16384 + sw, Alo    + arow + ka);
            cpa16(ab + 32768 + sw, g_wthi + brow + ka);
            cpa16(ab + 49152 + sw, g_wtlo + brow + ka);
        }
        cpa_commit();
    };

    float acc[2][8][4];
#pragma unroll
    for (int i = 0; i < 2; i++)
#pragma unroll
        for (int j = 0; j < 8; j++)
#pragma unroll
            for (int q = 0; q < 4; q++) acc[i][j][q] = 0.f;

    load_chunk(0, 0);
    load_chunk(1, 1);

    // ldmatrix lane address components (element offsets within tile)
    const int a_r = (lane & 15);                 // fragment row within m16
    const int a_k = (lane >> 4) * 8;             // k-half
    const int b_n = (lane & 7) + ((lane >> 4) & 1) * 8;   // n within n16
    const int b_k = ((lane >> 3) & 1) * 8;       // k-half

    for (int c = 0; c < 16; c++) {
        const int s = c & 1;
        if (c == 15) cpa_wait<0>(); else cpa_wait<1>();
        __syncthreads();
        const uint32_t ab = sb + s * STAGE_BYTES;

#pragma unroll
        for (int ks = 0; ks < 4; ks++) {
            uint32_t ah[2][4], al[2][4], bh[4][4], bl[4][4];
#pragma unroll
            for (int i = 0; i < 2; i++) {
                const int row = mw * 32 + i * 16 + a_r;
                const uint32_t sw = sw128(row * 128 + (ks * 16 + a_k) * 2);
                ldm4(ah[i], ab + sw);
                ldm4(al[i], ab + 16384 + sw);
            }
#pragma unroll
            for (int jp = 0; jp < 4; jp++) {
                const int nr = nw * 64 + jp * 16 + b_n;
                const uint32_t sw = sw128(nr * 128 + (ks * 16 + b_k) * 2);
                ldm4(bh[jp], ab + 32768 + sw);
                ldm4(bl[jp], ab + 49152 + sw);
            }
#pragma unroll
            for (int i = 0; i < 2; i++)
#pragma unroll
                for (int j = 0; j < 8; j++) {
                    const int jp = j >> 1, jo = (j & 1) * 2;
                    mma16816(acc[i][j], ah[i], bh[jp][jo], bh[jp][jo + 1]);
                    mma16816(acc[i][j], ah[i], bl[jp][jo], bl[jp][jo + 1]);
                    mma16816(acc[i][j], al[i], bh[jp][jo], bh[jp][jo + 1]);
                }
        }
        __syncthreads();
        if (c + 2 < 16) load_chunk(c + 2, s);
    }

    // epilogue
    const int g  = lane >> 2;
    const int t2 = (lane & 3) * 2;
    float* Cq = (DST == 0) ? g_q : (DST == 1) ? g_k : g_v;
#pragma unroll
    for (int i = 0; i < 2; i++) {
#pragma unroll
        for (int half = 0; half < 2; half++) {
            const int row = m0 + mw * 32 + i * 16 + g + half * 8;
#pragma unroll
            for (int j = 0; j < 8; j++) {
                const int col = n0 + nw * 64 + j * 8 + t2;
                float2 v;
                v.x = acc[i][j][half * 2 + 0] + bias[col + 0];
                v.y = acc[i][j][half * 2 + 1] + bias[col + 1];
                if (MODE == 0) {
                    const int h  = col >> 6;
                    const int d  = col & 63;
                    const int bb = row >> 11, ss = row & 2047;
                    *(float2*)&Cq[(((size_t)(bb * NH + h)) * SQ + ss) * DH + d] = v;
                } else {
                    *(float2*)&Cout[(size_t)row * DM + col] = v;
                }
            }
        }
    }
}

// ---------------- flash attention (fp32, causal) ---------------------------
__global__ __launch_bounds__(128) void attn_kernel()
{
    __shared__ float Qs[64 * 64];
    __shared__ float KPs[64 * 64];
    __shared__ float Vs[64 * 64];

    const int qt  = (SQ / 64 - 1) - (int)blockIdx.x;
    const int h   = blockIdx.y;
    const int b   = blockIdx.z;
    const int tid = threadIdx.x;
    const int cg  = tid & 7;
    const int rg  = tid >> 3;
    const int key = rg & 7;

    const size_t base = (size_t)(b * NH + h) * SQ * DH;
    const float* Qg = g_q + base + (size_t)qt * 64 * DH;
    const float* Kg = g_k + base;
    const float* Vg = g_v + base;

#pragma unroll
    for (int i = 0; i < 8; i++) {
        const int f   = tid + (i << 7);
        const int row = f >> 4;
        const int c4  = f & 15;
        float4 v = *(const float4*)(Qg + row * DH + (c4 << 2));
        *(float4*)&Qs[row * 64 + ((c4 ^ (row & 7)) << 2)] = v;
    }

    float m_i[4], l_i[4], acc[4][8];
#pragma unroll
    for (int ii = 0; ii < 4; ii++) {
        m_i[ii] = -1e30f;
        l_i[ii] = 0.f;
#pragma unroll
        for (int mm = 0; mm < 8; mm++) acc[ii][mm] = 0.f;
    }

    for (int kt = 0; kt <= qt; kt++) {
        const float* Kt = Kg + (size_t)kt * 64 * DH;
        const float* Vt = Vg + (size_t)kt * 64 * DH;
#pragma unroll
        for (int i = 0; i < 8; i++) {
            const int f   = tid + (i << 7);
            const int row = f >> 4;
            const int c4  = f & 15;
            float4 kv = *(const float4*)(Kt + row * DH + (c4 << 2));
            *(float4*)&KPs[row * 64 + ((c4 ^ (row & 7)) << 2)] = kv;
            float4 vv = *(const float4*)(Vt + row * DH + (c4 << 2));
            *(float4*)&Vs[row * 64 + (c4 << 2)] = vv;
        }
        __syncthreads();

        float s[4][8];
#pragma unroll
        for (int ii = 0; ii < 4; ii++)
#pragma unroll
            for (int jj = 0; jj < 8; jj++) s[ii][jj] = 0.f;

#pragma unroll
        for (int d4 = 0; d4 < 16; d4++) {
            float4 qf[4], kf[8];
#pragma unroll
            for (int ii = 0; ii < 4; ii++)
                qf[ii] = *(const float4*)&Qs[(rg + (ii << 4)) * 64 + ((d4 ^ key) << 2)];
#pragma unroll
            for (int jj = 0; jj < 8; jj++)
                kf[jj] = *(const float4*)&KPs[(cg + (jj << 3)) * 64 + ((d4 ^ cg) << 2)];
#pragma unroll
            for (int ii = 0; ii < 4; ii++)
#pragma unroll
                for (int jj = 0; jj < 8; jj++)
                    s[ii][jj] += qf[ii].x * kf[jj].x + qf[ii].y * kf[jj].y +
                                 qf[ii].z * kf[jj].z + qf[ii].w * kf[jj].w;
        }

        float fs[4];
#pragma unroll
        for (int ii = 0; ii < 4; ii++) {
            float tm = -1e30f;
#pragma unroll
            for (int jj = 0; jj < 8; jj++) {
                float v = s[ii][jj] * 0.125f;
                if (kt == qt && (cg + (jj << 3)) > (rg + (ii << 4)))
                    v = -100000.0f;
                s[ii][jj] = v;
                tm = fmaxf(tm, v);
            }
            tm = fmaxf(tm, __shfl_xor_sync(0xffffffffu, tm, 1));
            tm = fmaxf(tm, __shfl_xor_sync(0xffffffffu, tm, 2));
            tm = fmaxf(tm, __shfl_xor_sync(0xffffffffu, tm, 4));
            const float mn = fmaxf(m_i[ii], tm);
            const float f  = __expf(m_i[ii] - mn);
            m_i[ii] = mn;
            fs[ii]  = f;
            float rs = 0.f;
#pragma unroll
            for (int jj = 0; jj < 8; jj++) {
                const float p = __expf(s[ii][jj] - mn);
                s[ii][jj] = p;
                rs += p;
            }
            rs += __shfl_xor_sync(0xffffffffu, rs, 1);
            rs += __shfl_xor_sync(0xffffffffu, rs, 2);
            rs += __shfl_xor_sync(0xffffffffu, rs, 4);
            l_i[ii] = l_i[ii] * f + rs;
#pragma unroll
            for (int mm = 0; mm < 8; mm++) acc[ii][mm] *= fs[ii];
        }
        __syncthreads();

#pragma unroll
        for (int ii = 0; ii < 4; ii++) {
            const int i = rg + (ii << 4);
#pragma unroll
            for (int jj = 0; jj < 8; jj++) {
                const int j = cg + (jj << 3);
                KPs[i * 64 + (((j >> 2) ^ key) << 2) + (j & 3)] = s[ii][jj];
            }
        }
        __syncthreads();

#pragma unroll
        for (int j4 = 0; j4 < 16; j4++) {
            float4 pf[4];
#pragma unroll
            for (int ii = 0; ii < 4; ii++)
                pf[ii] = *(const float4*)&KPs[(rg + (ii << 4)) * 64 + ((j4 ^ key) << 2)];
#pragma unroll
            for (int c = 0; c < 4; c++) {
                const int j = (j4 << 2) + c;
                float vv[8];
#pragma unroll
                for (int mm = 0; mm < 8; mm++)
                    vv[mm] = Vs[j * 64 + cg + (mm << 3)];
#pragma unroll
                for (int ii = 0; ii < 4; ii++) {
                    const float p = (c == 0) ? pf[ii].x : (c == 1) ? pf[ii].y
                                  : (c == 2) ? pf[ii].z : pf[ii].w;
#pragma unroll
                    for (int mm = 0; mm < 8; mm++)
                        acc[ii][mm] += p * vv[mm];
                }
            }
        }
        __syncthreads();
    }

    // write bf16 hi/lo directly (input to tensor-core O-proj)
#pragma unroll
    for (int ii = 0; ii < 4; ii++) {
        const float inv = 1.0f / l_i[ii];
        const int row   = b * SQ + qt * 64 + rg + (ii << 4);
#pragma unroll
        for (int mm = 0; mm < 8; mm++) {
            const float v = acc[ii][mm] * inv;
            const size_t idx = (size_t)row * DM + h * DH + cg + (mm << 3);
            __nv_bfloat16 hh = __float2bfloat16(v);
            g_ahi[idx] = hh;
            g_alo[idx] = __float2bfloat16(v - __bfloat162float(hh));
        }
    }
}

// ---------------------------------------------------------------------------
extern "C" void kernel_launch(void* const* d_in, const int* in_sizes, int n_in,
                              void* d_out, int out_size)
{
    const float* x  = (const float*)d_in[0];
    const float* Qw = (const float*)d_in[1];
    const float* Qb = (const float*)d_in[2];
    const float* Kw = (const float*)d_in[3];
    const float* Kb = (const float*)d_in[4];
    const float* Vw = (const float*)d_in[5];
    const float* Vb = (const float*)d_in[6];
    const float* Ow = (const float*)d_in[7];
    const float* Ob = (const float*)d_in[8];
    float* out = (float*)d_out;

    cudaFuncSetAttribute(tc_gemm<0, 0>, cudaFuncAttributeMaxDynamicSharedMemorySize, SMEMSZ);
    cudaFuncSetAttribute(tc_gemm<0, 1>, cudaFuncAttributeMaxDynamicSharedMemorySize, SMEMSZ);
    cudaFuncSetAttribute(tc_gemm<0, 2>, cudaFuncAttributeMaxDynamicSharedMemorySize, SMEMSZ);
    cudaFuncSetAttribute(tc_gemm<1, 0>, cudaFuncAttributeMaxDynamicSharedMemorySize, SMEMSZ);

    __nv_bfloat16 *xhi, *xlo, *ahi, *alo;
    cudaGetSymbolAddress((void**)&xhi, g_xhi);
    cudaGetSymbolAddress((void**)&xlo, g_xlo);
    cudaGetSymbolAddress((void**)&ahi, g_ahi);
    cudaGetSymbolAddress((void**)&alo, g_alo);

    const dim3 gg(DM / 128, ROWS / 128);  // (8, 64)
    const int cvtw_grid = DM * DM / 256;

    cvt_split<<<ROWS * DM / 1024, 256>>>(x, xhi, xlo);

    cvt_wT<1><<<cvtw_grid, 256>>>(Qw);
    tc_gemm<0, 0><<<gg, 256, SMEMSZ>>>(xhi, xlo, Qb, nullptr);
    cvt_wT<1><<<cvtw_grid, 256>>>(Kw);
    tc_gemm<0, 1><<<gg, 256, SMEMSZ>>>(xhi, xlo, Kb, nullptr);
    cvt_wT<1><<<cvtw_grid, 256>>>(Vw);
    tc_gemm<0, 2><<<gg, 256, SMEMSZ>>>(xhi, xlo, Vb, nullptr);

    attn_kernel<<<dim3(SQ / 64, NH, BT), 128>>>();

    cvt_wT<0><<<cvtw_grid, 256>>>(Ow);
    tc_gemm<1, 0><<<gg, 256, SMEMSZ>>>(ahi, alo, Ob, out);
}

// round 9
// speedup vs baseline: 2.2671x; 1.8868x over previous
#include <cuda_runtime.h>
#include <cuda_bf16.h>
#include <stdint.h>

#define SQ   2048
#define DM   1024
#define NH   16
#define DH   64
#define BT   4
#define ROWS (BT * SQ)   // 8192

// ---------------- scratch (device globals; no allocation allowed) ----------
__device__ __nv_bfloat16 g_qhi[(size_t)ROWS * DM];
__device__ __nv_bfloat16 g_qlo[(size_t)ROWS * DM];
__device__ __nv_bfloat16 g_khi[(size_t)ROWS * DM];
__device__ __nv_bfloat16 g_klo[(size_t)ROWS * DM];
__device__ __nv_bfloat16 g_vhi[(size_t)ROWS * DM];
__device__ __nv_bfloat16 g_vlo[(size_t)ROWS * DM];
__device__ __nv_bfloat16 g_xhi[(size_t)ROWS * DM];
__device__ __nv_bfloat16 g_xlo[(size_t)ROWS * DM];
__device__ __nv_bfloat16 g_ahi[(size_t)ROWS * DM];
__device__ __nv_bfloat16 g_alo[(size_t)ROWS * DM];
__device__ __nv_bfloat16 g_wthi[(size_t)DM * DM];
__device__ __nv_bfloat16 g_wtlo[(size_t)DM * DM];

// ---------------- PTX helpers (sm_103-safe: no tcgen05) --------------------
__device__ __forceinline__ uint32_t s2u(const void* p) {
    uint32_t a;
    asm("{ .reg .u64 t; cvta.to.shared.u64 t, %1; cvt.u32.u64 %0, t; }"
        : "=r"(a) : "l"(p));
    return a;
}
__device__ __forceinline__ void cpa16(uint32_t dst, const void* src) {
    asm volatile("cp.async.cg.shared.global [%0], [%1], 16;"
                 :: "r"(dst), "l"(src));
}
__device__ __forceinline__ void cpa_commit() {
    asm volatile("cp.async.commit_group;" ::: "memory");
}
template <int N>
__device__ __forceinline__ void cpa_wait() {
    asm volatile("cp.async.wait_group %0;" :: "n"(N) : "memory");
}
__device__ __forceinline__ void ldm4(uint32_t* r, uint32_t addr) {
    asm volatile("ldmatrix.sync.aligned.m8n8.x4.shared.b16 {%0,%1,%2,%3}, [%4];"
                 : "=r"(r[0]), "=r"(r[1]), "=r"(r[2]), "=r"(r[3]) : "r"(addr));
}
__device__ __forceinline__ void ldm4t(uint32_t* r, uint32_t addr) {
    asm volatile("ldmatrix.sync.aligned.m8n8.x4.trans.shared.b16 {%0,%1,%2,%3}, [%4];"
                 : "=r"(r[0]), "=r"(r[1]), "=r"(r[2]), "=r"(r[3]) : "r"(addr));
}
__device__ __forceinline__ void mma16816(float* c, const uint32_t* a,
                                         uint32_t b0, uint32_t b1) {
    asm volatile("mma.sync.aligned.m16n8k16.row.col.f32.bf16.bf16.f32 "
                 "{%0,%1,%2,%3}, {%4,%5,%6,%7}, {%8,%9}, {%0,%1,%2,%3};"
                 : "+f"(c[0]), "+f"(c[1]), "+f"(c[2]), "+f"(c[3])
                 : "r"(a[0]), "r"(a[1]), "r"(a[2]), "r"(a[3]),
                   "r"(b0), "r"(b1));
}
__device__ __forceinline__ uint32_t sw128(uint32_t off) {
    return off ^ ((off >> 3) & 0x70);
}
__device__ __forceinline__ uint32_t packbf(float x, float y) {
    __nv_bfloat16 h0 = __float2bfloat16(x), h1 = __float2bfloat16(y);
    return ((uint32_t)__bfloat16_as_ushort(h1) << 16) | __bfloat16_as_ushort(h0);
}

// MUFU-free exp: exp(x) via 2^t, deg-5 poly on [-0.5,0.5], rel err ~3e-6.
__device__ __forceinline__ float fexp(float x) {
    x = fmaxf(x, -87.0f);
    float t = x * 1.4426950408889634f;
    float z = t + 12582912.0f;                // round-to-nearest int (magic)
    float n = z - 12582912.0f;
    float f = t - n;
    float p = 0.00133336f;
    p = fmaf(p, f, 0.00961813f);
    p = fmaf(p, f, 0.05550411f);
    p = fmaf(p, f, 0.24022651f);
    p = fmaf(p, f, 0.69314718f);
    p = fmaf(p, f, 1.0f);
    int sc = (__float_as_int(z) + (127 - 0x4B400000)) << 23;   // 2^n bits
    return __int_as_float(sc) * p;
}

// ---------------- conversion kernels ---------------------------------------
__global__ void cvt_split(const float* __restrict__ s,
                          __nv_bfloat16* __restrict__ hi,
                          __nv_bfloat16* __restrict__ lo) {
    int i = blockIdx.x * blockDim.x + threadIdx.x;
    float4 v = ((const float4*)s)[i];
    __nv_bfloat16 h0 = __float2bfloat16(v.x), h1 = __float2bfloat16(v.y);
    __nv_bfloat16 h2 = __float2bfloat16(v.z), h3 = __float2bfloat16(v.w);
    __nv_bfloat16 l0 = __float2bfloat16(v.x - __bfloat162float(h0));
    __nv_bfloat16 l1 = __float2bfloat16(v.y - __bfloat162float(h1));
    __nv_bfloat16 l2 = __float2bfloat16(v.z - __bfloat162float(h2));
    __nv_bfloat16 l3 = __float2bfloat16(v.w - __bfloat162float(h3));
    ((__nv_bfloat162*)hi)[2 * i]     = __nv_bfloat162(h0, h1);
    ((__nv_bfloat162*)hi)[2 * i + 1] = __nv_bfloat162(h2, h3);
    ((__nv_bfloat162*)lo)[2 * i]     = __nv_bfloat162(l0, l1);
    ((__nv_bfloat162*)lo)[2 * i + 1] = __nv_bfloat162(l2, l3);
}

// Transpose + split weight into g_wthi/g_wtlo as [n][k] (k contiguous).
template <int QKV>
__global__ void cvt_wT(const float* __restrict__ W) {
    int id = blockIdx.x * blockDim.x + threadIdx.x;  // id = n*1024 + k
    int k = id & (DM - 1);
    int n = id >> 10;
    float v;
    if (QKV) v = W[(size_t)(n >> 6) * (DM * DH) + (size_t)k * DH + (n & 63)];
    else     v = W[(size_t)k * DM + n];
    __nv_bfloat16 h = __float2bfloat16(v);
    g_wthi[id] = h;
    g_wtlo[id] = __float2bfloat16(v - __bfloat162float(h));
}

// ---------------- HMMA GEMM ------------------------------------------------
// C(8192 x 1024) = A @ W^T + bias,  bf16-split 3-pass, fp32 accum.
// MODE 0: C -> split bf16 q/k/v (DST) in [b][h][s][d].  MODE 1: C -> fp32 out.
#define STAGE_BYTES 65536
#define SMEMSZ      (2 * STAGE_BYTES)

template <int MODE, int DST>
__global__ __launch_bounds__(256) void tc_gemm(
    const __nv_bfloat16* __restrict__ Ahi,
    const __nv_bfloat16* __restrict__ Alo,
    const float* __restrict__ bias,
    float* __restrict__ Cout)
{
    extern __shared__ char smem[];
    const uint32_t sb = s2u(smem);
    const int tid  = threadIdx.x;
    const int lane = tid & 31;
    const int wid  = tid >> 5;
    const int mw   = wid & 3;
    const int nw   = wid >> 2;
    const int n0 = blockIdx.x * 128;
    const int m0 = blockIdx.y * 128;

    auto load_chunk = [&](int c, int s) {
        const uint32_t ab = sb + s * STAGE_BYTES;
        const int row = tid >> 1;
        const size_t arow = (size_t)(m0 + row) * DM;
        const size_t brow = (size_t)(n0 + row) * DM;
        const size_t kof = (size_t)c * 64;
#pragma unroll
        for (int i = 0; i < 4; i++) {
            const int seg = ((tid & 1) << 2) + i;
            const uint32_t sw = sw128(row * 128 + seg * 16);
            const size_t ka = kof + seg * 8;
            cpa16(ab + sw,         Ahi    + arow + ka);
            cpa16(ab + 16384 + sw, Alo    + arow + ka);
            cpa16(ab + 32768 + sw, g_wthi + brow + ka);
            cpa16(ab + 49152 + sw, g_wtlo + brow + ka);
        }
        cpa_commit();
    };

    float acc[2][8][4];
#pragma unroll
    for (int i = 0; i < 2; i++)
#pragma unroll
        for (int j = 0; j < 8; j++)
#pragma unroll
            for (int q = 0; q < 4; q++) acc[i][j][q] = 0.f;

    load_chunk(0, 0);
    load_chunk(1, 1);

    const int a_r = (lane & 15);
    const int a_k = (lane >> 4) * 8;
    const int b_n = (lane & 7) + ((lane >> 4) & 1) * 8;
    const int b_k = ((lane >> 3) & 1) * 8;

    for (int c = 0; c < 16; c++) {
        const int s = c & 1;
        if (c == 15) cpa_wait<0>(); else cpa_wait<1>();
        __syncthreads();
        const uint32_t ab = sb + s * STAGE_BYTES;

#pragma unroll
        for (int ks = 0; ks < 4; ks++) {
            uint32_t ah[2][4], al[2][4], bh[4][4], bl[4][4];
#pragma unroll
            for (int i = 0; i < 2; i++) {
                const int row = mw * 32 + i * 16 + a_r;
                const uint32_t sw = sw128(row * 128 + (ks * 16 + a_k) * 2);
                ldm4(ah[i], ab + sw);
                ldm4(al[i], ab + 16384 + sw);
            }
#pragma unroll
            for (int jp = 0; jp < 4; jp++) {
                const int nr = nw * 64 + jp * 16 + b_n;
                const uint32_t sw = sw128(nr * 128 + (ks * 16 + b_k) * 2);
                ldm4(bh[jp], ab + 32768 + sw);
                ldm4(bl[jp], ab + 49152 + sw);
            }
#pragma unroll
            for (int i = 0; i < 2; i++)
#pragma unroll
                for (int j = 0; j < 8; j++) {
                    const int jp = j >> 1, jo = (j & 1) * 2;
                    mma16816(acc[i][j], ah[i], bh[jp][jo], bh[jp][jo + 1]);
                    mma16816(acc[i][j], ah[i], bl[jp][jo], bl[jp][jo + 1]);
                    mma16816(acc[i][j], al[i], bh[jp][jo], bh[jp][jo + 1]);
                }
        }
        __syncthreads();
        if (c + 2 < 16) load_chunk(c + 2, s);
    }

    // epilogue
    const int g  = lane >> 2;
    const int t2 = (lane & 3) * 2;
    __nv_bfloat16* Hi = (DST == 0) ? g_qhi : (DST == 1) ? g_khi : g_vhi;
    __nv_bfloat16* Lo = (DST == 0) ? g_qlo : (DST == 1) ? g_klo : g_vlo;
#pragma unroll
    for (int i = 0; i < 2; i++) {
#pragma unroll
        for (int half = 0; half < 2; half++) {
            const int row = m0 + mw * 32 + i * 16 + g + half * 8;
#pragma unroll
            for (int j = 0; j < 8; j++) {
                const int col = n0 + nw * 64 + j * 8 + t2;
                float vx = acc[i][j][half * 2 + 0] + bias[col + 0];
                float vy = acc[i][j][half * 2 + 1] + bias[col + 1];
                if (MODE == 0) {
                    const int hh = col >> 6;
                    const int d  = col & 63;
                    const int bb = row >> 11, ss = row & 2047;
                    const size_t idx = (((size_t)(bb * NH + hh)) * SQ + ss) * DH + d;
                    __nv_bfloat16 h0 = __float2bfloat16(vx);
                    __nv_bfloat16 h1 = __float2bfloat16(vy);
                    *(uint32_t*)&Hi[idx] =
                        ((uint32_t)__bfloat16_as_ushort(h1) << 16) | __bfloat16_as_ushort(h0);
                    *(uint32_t*)&Lo[idx] =
                        packbf(vx - __bfloat162float(h0), vy - __bfloat162float(h1));
                } else {
                    float2 v; v.x = vx; v.y = vy;
                    *(float2*)&Cout[(size_t)row * DM + col] = v;
                }
            }
        }
    }
}

// ---------------- flash attention (HMMA bf16-split, causal) ----------------
// Block: 128 q-rows (4 warps x 32), k-tiles of 64, double-buffered cp.async.
// smem: Qhi[0,16K) Qlo[16K,32K); stage s at 32K+s*32K: Khi/Klo/Vhi/Vlo 8K each.
#define ATTN_SMEM (32768 + 2 * 32768)

__global__ __launch_bounds__(128, 2) void attn_kernel()
{
    extern __shared__ char smem[];
    const uint32_t sb = s2u(smem);
    const int qt   = (SQ / 128 - 1) - (int)blockIdx.x;   // heavy tiles first
    const int h    = blockIdx.y;
    const int b    = blockIdx.z;
    const int tid  = threadIdx.x;
    const int lane = tid & 31;
    const int warp = tid >> 5;
    const int g    = lane >> 2;
    const int t2   = (lane & 3) * 2;

    const size_t base = ((size_t)(b * NH + h)) * SQ * DH;

    const int a_r = lane & 15;
    const int a_k = (lane >> 4) * 8;
    const int b_n = (lane & 7) + ((lane >> 4) & 1) * 8;
    const int b_k = ((lane >> 3) & 1) * 8;
    const int v_m = lane >> 3, v_r = lane & 7;

    // load Q tile (hi/lo), 128 rows x 128B each buffer
#pragma unroll
    for (int rep = 0; rep < 8; rep++) {
        const int gi  = tid + rep * 128;
        const int row = gi >> 3;
        const int seg = gi & 7;
        const uint32_t sw = sw128(row * 128 + seg * 16);
        const size_t src = base + (size_t)(qt * 128 + row) * DH + seg * 8;
        cpa16(sb + sw,         g_qhi + src);
        cpa16(sb + 16384 + sw, g_qlo + src);
    }

    auto load_kv = [&](int kt, int s) {
        const uint32_t st = sb + 32768 + s * 32768;
        const int row = tid >> 1;
        const size_t soff = base + (size_t)(kt * 64 + row) * DH;
#pragma unroll
        for (int q = 0; q < 4; q++) {
            const int seg = (tid & 1) * 4 + q;
            const uint32_t sw = sw128(row * 128 + seg * 16);
            cpa16(st + sw,         g_khi + soff + seg * 8);
            cpa16(st + 8192 + sw,  g_klo + soff + seg * 8);
            cpa16(st + 16384 + sw, g_vhi + soff + seg * 8);
            cpa16(st + 24576 + sw, g_vlo + soff + seg * 8);
        }
    };

    load_kv(0, 0);
    cpa_commit();          // group0 = Q + kv(0)
    load_kv(1, 1);
    cpa_commit();          // group1 = kv(1)

    float o[2][8][4];
    float mi[2][2], li[2][2];
#pragma unroll
    for (int i = 0; i < 2; i++) {
#pragma unroll
        for (int j = 0; j < 8; j++)
#pragma unroll
            for (int q = 0; q < 4; q++) o[i][j][q] = 0.f;
        mi[i][0] = mi[i][1] = -1e30f;
        li[i][0] = li[i][1] = 0.f;
    }

    const int ktmax = 2 * qt + 1;
    for (int kt = 0; kt <= ktmax; kt++) {
        const int s = kt & 1;
        const uint32_t st = sb + 32768 + s * 32768;
        if (kt == ktmax) cpa_wait<0>(); else cpa_wait<1>();
        __syncthreads();

        // ---- S = Q K^T (3-pass split) ----
        float sf[2][8][4];
#pragma unroll
        for (int i = 0; i < 2; i++)
#pragma unroll
            for (int j = 0; j < 8; j++)
#pragma unroll
                for (int q = 0; q < 4; q++) sf[i][j][q] = 0.f;

#pragma unroll
        for (int ks = 0; ks < 4; ks++) {
            uint32_t ah[2][4], al[2][4], bh[4][4], bl[4][4];
#pragma unroll
            for (int i = 0; i < 2; i++) {
                const int row = warp * 32 + i * 16 + a_r;
                const uint32_t sw = sw128(row * 128 + (ks * 16 + a_k) * 2);
                ldm4(ah[i], sb + sw);
                ldm4(al[i], sb + 16384 + sw);
            }
#pragma unroll
            for (int jp = 0; jp < 4; jp++) {
                const int nr = jp * 16 + b_n;
                const uint32_t sw = sw128(nr * 128 + (ks * 16 + b_k) * 2);
                ldm4(bh[jp], st + sw);
                ldm4(bl[jp], st + 8192 + sw);
            }
#pragma unroll
            for (int i = 0; i < 2; i++)
#pragma unroll
                for (int j = 0; j < 8; j++) {
                    const int jp = j >> 1, jo = (j & 1) * 2;
                    mma16816(sf[i][j], ah[i], bh[jp][jo], bh[jp][jo + 1]);
                    mma16816(sf[i][j], ah[i], bl[jp][jo], bl[jp][jo + 1]);
                    mma16816(sf[i][j], al[i], bh[jp][jo], bh[jp][jo + 1]);
                }
        }

        // ---- online softmax (MUFU-free exp) ----
        const bool diag = (kt >= 2 * qt);
#pragma unroll
        for (int i = 0; i < 2; i++)
#pragma unroll
            for (int hf = 0; hf < 2; hf++) {
                const int grow = qt * 128 + warp * 32 + i * 16 + g + hf * 8;
                float mx = -1e30f;
#pragma unroll
                for (int j = 0; j < 8; j++)
#pragma unroll
                    for (int q2 = 0; q2 < 2; q2++) {
                        float v = sf[i][j][hf * 2 + q2] * 0.125f;
                        if (diag && (kt * 64 + j * 8 + t2 + q2) > grow)
                            v = -100000.0f;
                        sf[i][j][hf * 2 + q2] = v;
                        mx = fmaxf(mx, v);
                    }
                mx = fmaxf(mx, __shfl_xor_sync(0xffffffffu, mx, 1));
                mx = fmaxf(mx, __shfl_xor_sync(0xffffffffu, mx, 2));
                const float mn = fmaxf(mi[i][hf], mx);
                const float fs = fexp(mi[i][hf] - mn);
                mi[i][hf] = mn;
                float rs = 0.f;
#pragma unroll
                for (int j = 0; j < 8; j++)
#pragma unroll
                    for (int q2 = 0; q2 < 2; q2++) {
                        const float p = fexp(sf[i][j][hf * 2 + q2] - mn);
                        sf[i][j][hf * 2 + q2] = p;
                        rs += p;
                    }
                rs += __shfl_xor_sync(0xffffffffu, rs, 1);
                rs += __shfl_xor_sync(0xffffffffu, rs, 2);
                li[i][hf] = li[i][hf] * fs + rs;
#pragma unroll
                for (int j = 0; j < 8; j++) {
                    o[i][j][hf * 2 + 0] *= fs;
                    o[i][j][hf * 2 + 1] *= fs;
                }
            }

        // ---- O += P V (3-pass split; V via ldmatrix.trans) ----
#pragma unroll
        for (int ks = 0; ks < 4; ks++) {
            uint32_t vh[4][4], vl[4][4];
#pragma unroll
            for (int dp = 0; dp < 4; dp++) {
                const int srow = ks * 16 + (v_m & 1) * 8 + v_r;
                const int dcol = dp * 16 + (v_m >> 1) * 8;
                const uint32_t sw = sw128(srow * 128 + dcol * 2);
                ldm4t(vh[dp], st + 16384 + sw);
                ldm4t(vl[dp], st + 24576 + sw);
            }
#pragma unroll
            for (int i = 0; i < 2; i++) {
                uint32_t ph[4], pl[4];
#pragma unroll
                for (int r = 0; r < 4; r++) {
                    const int j  = ks * 2 + (r >> 1);
                    const int q0 = (r & 1) * 2;
                    const float x0 = sf[i][j][q0], x1 = sf[i][j][q0 + 1];
                    const __nv_bfloat16 h0 = __float2bfloat16(x0);
                    const __nv_bfloat16 h1 = __float2bfloat16(x1);
                    ph[r] = ((uint32_t)__bfloat16_as_ushort(h1) << 16)
                          | __bfloat16_as_ushort(h0);
                    pl[r] = packbf(x0 - __bfloat162float(h0),
                                   x1 - __bfloat162float(h1));
                }
#pragma unroll
                for (int dp = 0; dp < 4; dp++) {
                    mma16816(o[i][2 * dp],     ph, vh[dp][0], vh[dp][1]);
                    mma16816(o[i][2 * dp],     ph, vl[dp][0], vl[dp][1]);
                    mma16816(o[i][2 * dp],     pl, vh[dp][0], vh[dp][1]);
                    mma16816(o[i][2 * dp + 1], ph, vh[dp][2], vh[dp][3]);
                    mma16816(o[i][2 * dp + 1], ph, vl[dp][2], vl[dp][3]);
                    mma16816(o[i][2 * dp + 1], pl, vh[dp][2], vh[dp][3]);
                }
            }
        }

        __syncthreads();
        if (kt + 2 <= ktmax) load_kv(kt + 2, s);
        cpa_commit();
    }

    // ---- epilogue: O/l -> bf16 hi/lo for the O-proj GEMM ----
#pragma unroll
    for (int i = 0; i < 2; i++)
#pragma unroll
        for (int hf = 0; hf < 2; hf++) {
            const float inv = 1.0f / li[i][hf];
            const size_t row = (size_t)b * SQ + qt * 128 + warp * 32 + i * 16 + g + hf * 8;
#pragma unroll
            for (int j = 0; j < 8; j++) {
                const float x0 = o[i][j][hf * 2 + 0] * inv;
                const float x1 = o[i][j][hf * 2 + 1] * inv;
                const size_t idx = row * DM + h * DH + j * 8 + t2;
                const __nv_bfloat16 h0 = __float2bfloat16(x0);
                const __nv_bfloat16 h1 = __float2bfloat16(x1);
                *(uint32_t*)&g_ahi[idx] =
                    ((uint32_t)__bfloat16_as_ushort(h1) << 16) | __bfloat16_as_ushort(h0);
                *(uint32_t*)&g_alo[idx] =
                    packbf(x0 - __bfloat162float(h0), x1 - __bfloat162float(h1));
            }
        }
}

// ---------------------------------------------------------------------------
extern "C" void kernel_launch(void* const* d_in, const int* in_sizes, int n_in,
                              void* d_out, int out_size)
{
    const float* x  = (const float*)d_in[0];
    const float* Qw = (const float*)d_in[1];
    const float* Qb = (const float*)d_in[2];
    const float* Kw = (const float*)d_in[3];
    const float* Kb = (const float*)d_in[4];
    const float* Vw = (const float*)d_in[5];
    const float* Vb = (const float*)d_in[6];
    const float* Ow = (const float*)d_in[7];
    const float* Ob = (const float*)d_in[8];
    float* out = (float*)d_out;

    cudaFuncSetAttribute(tc_gemm<0, 0>, cudaFuncAttributeMaxDynamicSharedMemorySize, SMEMSZ);
    cudaFuncSetAttribute(tc_gemm<0, 1>, cudaFuncAttributeMaxDynamicSharedMemorySize, SMEMSZ);
    cudaFuncSetAttribute(tc_gemm<0, 2>, cudaFuncAttributeMaxDynamicSharedMemorySize, SMEMSZ);
    cudaFuncSetAttribute(tc_gemm<1, 0>, cudaFuncAttributeMaxDynamicSharedMemorySize, SMEMSZ);
    cudaFuncSetAttribute(attn_kernel, cudaFuncAttributeMaxDynamicSharedMemorySize, ATTN_SMEM);

    __nv_bfloat16 *xhi, *xlo, *ahi, *alo;
    cudaGetSymbolAddress((void**)&xhi, g_xhi);
    cudaGetSymbolAddress((void**)&xlo, g_xlo);
    cudaGetSymbolAddress((void**)&ahi, g_ahi);
    cudaGetSymbolAddress((void**)&alo, g_alo);

    const dim3 gg(DM / 128, ROWS / 128);  // (8, 64)
    const int cvtw_grid = DM * DM / 256;

    cvt_split<<<ROWS * DM / 1024, 256>>>(x, xhi, xlo);

    cvt_wT<1><<<cvtw_grid, 256>>>(Qw);
    tc_gemm<0, 0><<<gg, 256, SMEMSZ>>>(xhi, xlo, Qb, nullptr);
    cvt_wT<1><<<cvtw_grid, 256>>>(Kw);
    tc_gemm<0, 1><<<gg, 256, SMEMSZ>>>(xhi, xlo, Kb, nullptr);
    cvt_wT<1><<<cvtw_grid, 256>>>(Vw);
    tc_gemm<0, 2><<<gg, 256, SMEMSZ>>>(xhi, xlo, Vb, nullptr);

    attn_kernel<<<dim3(SQ / 128, NH, BT), 128, ATTN_SMEM>>>();

    cvt_wT<0><<<cvtw_grid, 256>>>(Ow);
    tc_gemm<1, 0><<<gg, 256, SMEMSZ>>>(ahi, alo, Ob, out);
}

// round 13
// speedup vs baseline: 3.5879x; 1.5826x over previous
#include <cuda_runtime.h>
#include <cuda_fp16.h>
#include <stdint.h>

#define SQ   2048
#define DM   1024
#define NH   16
#define DH   64
#define BT   4
#define ROWS (BT * SQ)   // 8192

// ---------------- scratch (device globals; no allocation allowed) ----------
__device__ __half g_qhi[(size_t)ROWS * DM];
__device__ __half g_qlo[(size_t)ROWS * DM];
__device__ __half g_kf [(size_t)ROWS * DM];
__device__ __half g_vf [(size_t)ROWS * DM];
__device__ __half g_xhi[(size_t)ROWS * DM];
__device__ __half g_xlo[(size_t)ROWS * DM];
__device__ __half g_ahi[(size_t)ROWS * DM];
__device__ __half g_alo[(size_t)ROWS * DM];
__device__ __half g_wt [(size_t)3 * DM * DM];   // [n_global][k], n<3072 (QKV) / n<1024 (O)

// ---------------- PTX helpers (sm_103-safe: no tcgen05) --------------------
__device__ __forceinline__ uint32_t s2u(const void* p) {
    uint32_t a;
    asm("{ .reg .u64 t; cvta.to.shared.u64 t, %1; cvt.u32.u64 %0, t; }"
        : "=r"(a) : "l"(p));
    return a;
}
__device__ __forceinline__ void cpa16(uint32_t dst, const void* src) {
    asm volatile("cp.async.cg.shared.global [%0], [%1], 16;"
                 :: "r"(dst), "l"(src));
}
__device__ __forceinline__ void cpa_commit() {
    asm volatile("cp.async.commit_group;" ::: "memory");
}
template <int N>
__device__ __forceinline__ void cpa_wait() {
    asm volatile("cp.async.wait_group %0;" :: "n"(N) : "memory");
}
__device__ __forceinline__ void ldm4(uint32_t* r, uint32_t addr) {
    asm volatile("ldmatrix.sync.aligned.m8n8.x4.shared.b16 {%0,%1,%2,%3}, [%4];"
                 : "=r"(r[0]), "=r"(r[1]), "=r"(r[2]), "=r"(r[3]) : "r"(addr));
}
__device__ __forceinline__ void ldm4t(uint32_t* r, uint32_t addr) {
    asm volatile("ldmatrix.sync.aligned.m8n8.x4.trans.shared.b16 {%0,%1,%2,%3}, [%4];"
                 : "=r"(r[0]), "=r"(r[1]), "=r"(r[2]), "=r"(r[3]) : "r"(addr));
}
__device__ __forceinline__ void mma16816(float* c, const uint32_t* a,
                                         uint32_t b0, uint32_t b1) {
    asm volatile("mma.sync.aligned.m16n8k16.row.col.f32.f16.f16.f32 "
                 "{%0,%1,%2,%3}, {%4,%5,%6,%7}, {%8,%9}, {%0,%1,%2,%3};"
                 : "+f"(c[0]), "+f"(c[1]), "+f"(c[2]), "+f"(c[3])
                 : "r"(a[0]), "r"(a[1]), "r"(a[2]), "r"(a[3]),
                   "r"(b0), "r"(b1));
}
__device__ __forceinline__ uint32_t sw128(uint32_t off) {
    return off ^ ((off >> 3) & 0x70);
}
__device__ __forceinline__ uint32_t packh(float x, float y) {
    __half h0 = __float2half_rn(x), h1 = __float2half_rn(y);
    return ((uint32_t)__half_as_ushort(h1) << 16) | __half_as_ushort(h0);
}

// MUFU-free exp: exp(x) via 2^t, deg-5 poly on [-0.5,0.5], rel err ~3e-6.
__device__ __forceinline__ float fexp(float x) {
    x = fmaxf(x, -87.0f);
    float t = x * 1.4426950408889634f;
    float z = t + 12582912.0f;                // round-to-nearest int (magic)
    float n = z - 12582912.0f;
    float f = t - n;
    float p = 0.00133336f;
    p = fmaf(p, f, 0.00961813f);
    p = fmaf(p, f, 0.05550411f);
    p = fmaf(p, f, 0.24022651f);
    p = fmaf(p, f, 0.69314718f);
    p = fmaf(p, f, 1.0f);
    int sc = (__float_as_int(z) + (127 - 0x4B400000)) << 23;   // 2^n bits
    return __int_as_float(sc) * p;
}

// ---------------- conversion kernels ---------------------------------------
// x -> fp16 hi/lo split
__global__ void cvt_split(const float* __restrict__ s,
                          __half* __restrict__ hi,
                          __half* __restrict__ lo) {
    int i = blockIdx.x * blockDim.x + threadIdx.x;
    float4 v = ((const float4*)s)[i];
    __half h0 = __float2half_rn(v.x), h1 = __float2half_rn(v.y);
    __half h2 = __float2half_rn(v.z), h3 = __float2half_rn(v.w);
    uint32_t hp0 = ((uint32_t)__half_as_ushort(h1) << 16) | __half_as_ushort(h0);
    uint32_t hp1 = ((uint32_t)__half_as_ushort(h3) << 16) | __half_as_ushort(h2);
    ((uint32_t*)hi)[2 * i]     = hp0;
    ((uint32_t*)hi)[2 * i + 1] = hp1;
    ((uint32_t*)lo)[2 * i]     = packh(v.x - __half2float(h0), v.y - __half2float(h1));
    ((uint32_t*)lo)[2 * i + 1] = packh(v.z - __half2float(h2), v.w - __half2float(h3));
}

// all three QKV weights -> g_wt fp16 [n_global][k], n_global = w*1024 + h*64+d
__global__ void cvt_wqkv(const float* __restrict__ Qw,
                         const float* __restrict__ Kw,
                         const float* __restrict__ Vw) {
    int id = blockIdx.x * blockDim.x + threadIdx.x;   // id = n_global*1024 + k
    int k = id & (DM - 1);
    int n = (id >> 10) & (DM - 1);
    int w = id >> 20;
    const float* W = (w == 0) ? Qw : (w == 1) ? Kw : Vw;
    float v = W[(size_t)(n >> 6) * (DM * DH) + (size_t)k * DH + (n & 63)];
    g_wt[id] = __float2half_rn(v);
}

// O_w [k][n] -> g_wt [n][k]
__global__ void cvt_wo(const float* __restrict__ W) {
    int id = blockIdx.x * blockDim.x + threadIdx.x;   // id = n*1024 + k
    int k = id & (DM - 1);
    int n = id >> 10;
    g_wt[id] = __float2half_rn(W[(size_t)k * DM + n]);
}

// ---------------- fused QKV GEMM (fp16 2-pass) ------------------------------
// C(8192 x 3072) = X @ Wqkv^T + bias; X split fp16 hi/lo, W single fp16.
// 128x128 tile, 256 thr, warp tile 32x64; K-chunk 64, 2-stage cp.async.
// Q cols (n<1024) -> split hi/lo; K (1024..2047), V (2048..3071) -> single fp16.
#define G_STAGE 49152              // Ahi 16K | Alo 16K | B 16K
#define G_SMEM  (2 * G_STAGE)

__global__ __launch_bounds__(256) void qkv_gemm(
    const __half* __restrict__ Ahi,
    const __half* __restrict__ Alo,
    const float* __restrict__ Qb,
    const float* __restrict__ Kb,
    const float* __restrict__ Vb)
{
    extern __shared__ char smem[];
    const uint32_t sb = s2u(smem);
    const int tid  = threadIdx.x;
    const int lane = tid & 31;
    const int wid  = tid >> 5;
    const int mw   = wid & 3;
    const int nw   = wid >> 2;
    const int n0 = blockIdx.x * 128;
    const int m0 = blockIdx.y * 128;

    auto load_chunk = [&](int c, int s) {
        const uint32_t ab = sb + s * G_STAGE;
        const int row = tid >> 1;
        const size_t arow = (size_t)(m0 + row) * DM;
        const size_t brow = (size_t)(n0 + row) * DM;
        const size_t kof = (size_t)c * 64;
#pragma unroll
        for (int i = 0; i < 4; i++) {
            const int seg = ((tid & 1) << 2) + i;
            const uint32_t sw = sw128(row * 128 + seg * 16);
            const size_t ka = kof + seg * 8;
            cpa16(ab + sw,         Ahi  + arow + ka);
            cpa16(ab + 16384 + sw, Alo  + arow + ka);
            cpa16(ab + 32768 + sw, g_wt + brow + ka);
        }
        cpa_commit();
    };

    float acc[2][8][4];
#pragma unroll
    for (int i = 0; i < 2; i++)
#pragma unroll
        for (int j = 0; j < 8; j++)
#pragma unroll
            for (int q = 0; q < 4; q++) acc[i][j][q] = 0.f;

    load_chunk(0, 0);
    load_chunk(1, 1);

    const int a_r = (lane & 15);
    const int a_k = (lane >> 4) * 8;
    const int b_n = (lane & 7) + ((lane >> 4) & 1) * 8;
    const int b_k = ((lane >> 3) & 1) * 8;

    for (int c = 0; c < 16; c++) {
        const int s = c & 1;
        if (c == 15) cpa_wait<0>(); else cpa_wait<1>();
        __syncthreads();
        const uint32_t ab = sb + s * G_STAGE;

#pragma unroll
        for (int ks = 0; ks < 4; ks++) {
            uint32_t ah[2][4], al[2][4], bh[4][4];
#pragma unroll
            for (int i = 0; i < 2; i++) {
                const int row = mw * 32 + i * 16 + a_r;
                const uint32_t sw = sw128(row * 128 + (ks * 16 + a_k) * 2);
                ldm4(ah[i], ab + sw);
                ldm4(al[i], ab + 16384 + sw);
            }
#pragma unroll
            for (int jp = 0; jp < 4; jp++) {
                const int nr = nw * 64 + jp * 16 + b_n;
                const uint32_t sw = sw128(nr * 128 + (ks * 16 + b_k) * 2);
                ldm4(bh[jp], ab + 32768 + sw);
            }
#pragma unroll
            for (int i = 0; i < 2; i++)
#pragma unroll
                for (int j = 0; j < 8; j++) {
                    const int jp = j >> 1, jo = (j & 1) * 2;
                    mma16816(acc[i][j], ah[i], bh[jp][jo], bh[jp][jo + 1]);
                    mma16816(acc[i][j], al[i], bh[jp][jo], bh[jp][jo + 1]);
                }
        }
        __syncthreads();
        if (c + 2 < 16) load_chunk(c + 2, s);
    }

    // epilogue: n<1024 -> Q split; n<2048 -> K fp16; else V fp16
    const int g  = lane >> 2;
    const int t2 = (lane & 3) * 2;
#pragma unroll
    for (int i = 0; i < 2; i++) {
#pragma unroll
        for (int half = 0; half < 2; half++) {
            const int row = m0 + mw * 32 + i * 16 + g + half * 8;
            const int bb = row >> 11, ss = row & 2047;
#pragma unroll
            for (int j = 0; j < 8; j++) {
                const int col = n0 + nw * 64 + j * 8 + t2;
                const int sel = col >> 10;
                const int c1  = col & 1023;
                const float* bias = (sel == 0) ? Qb : (sel == 1) ? Kb : Vb;
                float vx = acc[i][j][half * 2 + 0] + bias[c1 + 0];
                float vy = acc[i][j][half * 2 + 1] + bias[c1 + 1];
                const int hh = c1 >> 6;
                const int d  = c1 & 63;
                const size_t idx = (((size_t)(bb * NH + hh)) * SQ + ss) * DH + d;
                if (sel == 0) {
                    __half h0 = __float2half_rn(vx);
                    __half h1 = __float2half_rn(vy);
                    *(uint32_t*)&g_qhi[idx] =
                        ((uint32_t)__half_as_ushort(h1) << 16) | __half_as_ushort(h0);
                    *(uint32_t*)&g_qlo[idx] =
                        packh(vx - __half2float(h0), vy - __half2float(h1));
                } else if (sel == 1) {
                    *(uint32_t*)&g_kf[idx] = packh(vx, vy);
                } else {
                    *(uint32_t*)&g_vf[idx] = packh(vx, vy);
                }
            }
        }
    }
}

// ---------------- O-projection GEMM (fp16 2-pass) ---------------------------
__global__ __launch_bounds__(256) void o_gemm(
    const __half* __restrict__ Ahi,
    const __half* __restrict__ Alo,
    const float* __restrict__ bias,
    float* __restrict__ Cout)
{
    extern __shared__ char smem[];
    const uint32_t sb = s2u(smem);
    const int tid  = threadIdx.x;
    const int lane = tid & 31;
    const int wid  = tid >> 5;
    const int mw   = wid & 3;
    const int nw   = wid >> 2;
    const int n0 = blockIdx.x * 128;
    const int m0 = blockIdx.y * 128;

    auto load_chunk = [&](int c, int s) {
        const uint32_t ab = sb + s * G_STAGE;
        const int row = tid >> 1;
        const size_t arow = (size_t)(m0 + row) * DM;
        const size_t brow = (size_t)(n0 + row) * DM;
        const size_t kof = (size_t)c * 64;
#pragma unroll
        for (int i = 0; i < 4; i++) {
            const int seg = ((tid & 1) << 2) + i;
            const uint32_t sw = sw128(row * 128 + seg * 16);
            const size_t ka = kof + seg * 8;
            cpa16(ab + sw,         Ahi  + arow + ka);
            cpa16(ab + 16384 + sw, Alo  + arow + ka);
            cpa16(ab + 32768 + sw, g_wt + brow + ka);
        }
        cpa_commit();
    };

    float acc[2][8][4];
#pragma unroll
    for (int i = 0; i < 2; i++)
#pragma unroll
        for (int j = 0; j < 8; j++)
#pragma unroll
            for (int q = 0; q < 4; q++) acc[i][j][q] = 0.f;

    load_chunk(0, 0);
    load_chunk(1, 1);

    const int a_r = (lane & 15);
    const int a_k = (lane >> 4) * 8;
    const int b_n = (lane & 7) + ((lane >> 4) & 1) * 8;
    const int b_k = ((lane >> 3) & 1) * 8;

    for (int c = 0; c < 16; c++) {
        const int s = c & 1;
        if (c == 15) cpa_wait<0>(); else cpa_wait<1>();
        __syncthreads();
        const uint32_t ab = sb + s * G_STAGE;

#pragma unroll
        for (int ks = 0; ks < 4; ks++) {
            uint32_t ah[2][4], al[2][4], bh[4][4];
#pragma unroll
            for (int i = 0; i < 2; i++) {
                const int row = mw * 32 + i * 16 + a_r;
                const uint32_t sw = sw128(row * 128 + (ks * 16 + a_k) * 2);
                ldm4(ah[i], ab + sw);
                ldm4(al[i], ab + 16384 + sw);
            }
#pragma unroll
            for (int jp = 0; jp < 4; jp++) {
                const int nr = nw * 64 + jp * 16 + b_n;
                const uint32_t sw = sw128(nr * 128 + (ks * 16 + b_k) * 2);
                ldm4(bh[jp], ab + 32768 + sw);
            }
#pragma unroll
            for (int i = 0; i < 2; i++)
#pragma unroll
                for (int j = 0; j < 8; j++) {
                    const int jp = j >> 1, jo = (j & 1) * 2;
                    mma16816(acc[i][j], ah[i], bh[jp][jo], bh[jp][jo + 1]);
                    mma16816(acc[i][j], al[i], bh[jp][jo], bh[jp][jo + 1]);
                }
        }
        __syncthreads();
        if (c + 2 < 16) load_chunk(c + 2, s);
    }

    const int g  = lane >> 2;
    const int t2 = (lane & 3) * 2;
#pragma unroll
    for (int i = 0; i < 2; i++)
#pragma unroll
        for (int half = 0; half < 2; half++) {
            const int row = m0 + mw * 32 + i * 16 + g + half * 8;
#pragma unroll
            for (int j = 0; j < 8; j++) {
                const int col = n0 + nw * 64 + j * 8 + t2;
                float2 v;
                v.x = acc[i][j][half * 2 + 0] + bias[col + 0];
                v.y = acc[i][j][half * 2 + 1] + bias[col + 1];
                *(float2*)&Cout[(size_t)row * DM + col] = v;
            }
        }
}

// ---------------- flash attention (HMMA fp16 2-pass, causal) ----------------
// Block: 128 q-rows (4 warps), k-tiles of 64, double-buffered cp.async.
// smem: Qhi[0,16K) Qlo[16K,32K); stage s at 32K+s*16K: K 8K | V 8K.
#define ATTN_SMEM (32768 + 2 * 16384)

__global__ __launch_bounds__(128, 2) void attn_kernel()
{
    extern __shared__ char smem[];
    const uint32_t sb = s2u(smem);
    const int qt   = (SQ / 128 - 1) - (int)blockIdx.x;   // heavy tiles first
    const int h    = blockIdx.y;
    const int b    = blockIdx.z;
    const int tid  = threadIdx.x;
    const int lane = tid & 31;
    const int warp = tid >> 5;
    const int g    = lane >> 2;
    const int t2   = (lane & 3) * 2;

    const size_t base = ((size_t)(b * NH + h)) * SQ * DH;

    const int a_r = lane & 15;
    const int a_k = (lane >> 4) * 8;
    const int b_n = (lane & 7) + ((lane >> 4) & 1) * 8;
    const int b_k = ((lane >> 3) & 1) * 8;
    const int v_m = lane >> 3, v_r = lane & 7;

    // load Q tile (hi/lo)
#pragma unroll
    for (int rep = 0; rep < 8; rep++) {
        const int gi  = tid + rep * 128;
        const int row = gi >> 3;
        const int seg = gi & 7;
        const uint32_t sw = sw128(row * 128 + seg * 16);
        const size_t src = base + (size_t)(qt * 128 + row) * DH + seg * 8;
        cpa16(sb + sw,         g_qhi + src);
        cpa16(sb + 16384 + sw, g_qlo + src);
    }

    auto load_kv = [&](int kt, int s) {
        const uint32_t st = sb + 32768 + s * 16384;
        const int row = tid >> 1;
        const size_t soff = base + (size_t)(kt * 64 + row) * DH;
#pragma unroll
        for (int q = 0; q < 4; q++) {
            const int seg = (tid & 1) * 4 + q;
            const uint32_t sw = sw128(row * 128 + seg * 16);
            cpa16(st + sw,        g_kf + soff + seg * 8);
            cpa16(st + 8192 + sw, g_vf + soff + seg * 8);
        }
    };

    load_kv(0, 0);
    cpa_commit();          // group0 = Q + kv(0)
    load_kv(1, 1);
    cpa_commit();          // group1 = kv(1)

    float o[2][8][4];
    float mi[2][2], li[2][2];
#pragma unroll
    for (int i = 0; i < 2; i++) {
#pragma unroll
        for (int j = 0; j < 8; j++)
#pragma unroll
            for (int q = 0; q < 4; q++) o[i][j][q] = 0.f;
        mi[i][0] = mi[i][1] = -1e30f;
        li[i][0] = li[i][1] = 0.f;
    }

    const int ktmax = 2 * qt + 1;
    for (int kt = 0; kt <= ktmax; kt++) {
        const int s = kt & 1;
        const uint32_t st = sb + 32768 + s * 16384;
        if (kt == ktmax) cpa_wait<0>(); else cpa_wait<1>();
        __syncthreads();

        // ---- S = Q K^T (2-pass) ----
        float sf[2][8][4];
#pragma unroll
        for (int i = 0; i < 2; i++)
#pragma unroll
            for (int j = 0; j < 8; j++)
#pragma unroll
                for (int q = 0; q < 4; q++) sf[i][j][q] = 0.f;

#pragma unroll
        for (int ks = 0; ks < 4; ks++) {
            uint32_t ah[2][4], al[2][4], bh[4][4];
#pragma unroll
            for (int i = 0; i < 2; i++) {
                const int row = warp * 32 + i * 16 + a_r;
                const uint32_t sw = sw128(row * 128 + (ks * 16 + a_k) * 2);
                ldm4(ah[i], sb + sw);
                ldm4(al[i], sb + 16384 + sw);
            }
#pragma unroll
            for (int jp = 0; jp < 4; jp++) {
                const int nr = jp * 16 + b_n;
                const uint32_t sw = sw128(nr * 128 + (ks * 16 + b_k) * 2);
                ldm4(bh[jp], st + sw);
            }
#pragma unroll
            for (int i = 0; i < 2; i++)
#pragma unroll
                for (int j = 0; j < 8; j++) {
                    const int jp = j >> 1, jo = (j & 1) * 2;
                    mma16816(sf[i][j], ah[i], bh[jp][jo], bh[jp][jo + 1]);
                    mma16816(sf[i][j], al[i], bh[jp][jo], bh[jp][jo + 1]);
                }
        }

        // ---- online softmax (MUFU-free exp) ----
        const bool diag = (kt >= 2 * qt);
#pragma unroll
        for (int i = 0; i < 2; i++)
#pragma unroll
            for (int hf = 0; hf < 2; hf++) {
                const int grow = qt * 128 + warp * 32 + i * 16 + g + hf * 8;
                float mx = -1e30f;
#pragma unroll
                for (int j = 0; j < 8; j++)
#pragma unroll
                    for (int q2 = 0; q2 < 2; q2++) {
                        float v = sf[i][j][hf * 2 + q2] * 0.125f;
                        if (diag && (kt * 64 + j * 8 + t2 + q2) > grow)
                            v = -100000.0f;
                        sf[i][j][hf * 2 + q2] = v;
                        mx = fmaxf(mx, v);
                    }
                mx = fmaxf(mx, __shfl_xor_sync(0xffffffffu, mx, 1));
                mx = fmaxf(mx, __shfl_xor_sync(0xffffffffu, mx, 2));
                const float mn = fmaxf(mi[i][hf], mx);
                const float fs = fexp(mi[i][hf] - mn);
                mi[i][hf] = mn;
                float rs = 0.f;
#pragma unroll
                for (int j = 0; j < 8; j++)
#pragma unroll
                    for (int q2 = 0; q2 < 2; q2++) {
                        const float p = fexp(sf[i][j][hf * 2 + q2] - mn);
                        sf[i][j][hf * 2 + q2] = p;
                        rs += p;
                    }
                rs += __shfl_xor_sync(0xffffffffu, rs, 1);
                rs += __shfl_xor_sync(0xffffffffu, rs, 2);
                li[i][hf] = li[i][hf] * fs + rs;
#pragma unroll
                for (int j = 0; j < 8; j++) {
                    o[i][j][hf * 2 + 0] *= fs;
                    o[i][j][hf * 2 + 1] *= fs;
                }
            }

        // ---- O += P V (2-pass: P split fp16, V single; V via ldmatrix.trans) ----
#pragma unroll
        for (int ks = 0; ks < 4; ks++) {
            uint32_t vh[4][4];
#pragma unroll
            for (int dp = 0; dp < 4; dp++) {
                const int srow = ks * 16 + (v_m & 1) * 8 + v_r;
                const int dcol = dp * 16 + (v_m >> 1) * 8;
                const uint32_t sw = sw128(srow * 128 + dcol * 2);
                ldm4t(vh[dp], st + 8192 + sw);
            }
#pragma unroll
            for (int i = 0; i < 2; i++) {
                uint32_t ph[4], pl[4];
#pragma unroll
                for (int r = 0; r < 4; r++) {
                    const int j  = ks * 2 + (r >> 1);
                    const int q0 = (r & 1) * 2;
                    const float x0 = sf[i][j][q0], x1 = sf[i][j][q0 + 1];
                    const __half h0 = __float2half_rn(x0);
                    const __half h1 = __float2half_rn(x1);
                    ph[r] = ((uint32_t)__half_as_ushort(h1) << 16)
                          | __half_as_ushort(h0);
                    pl[r] = packh(x0 - __half2float(h0), x1 - __half2float(h1));
                }
#pragma unroll
                for (int dp = 0; dp < 4; dp++) {
                    mma16816(o[i][2 * dp],     ph, vh[dp][0], vh[dp][1]);
                    mma16816(o[i][2 * dp],     pl, vh[dp][0], vh[dp][1]);
                    mma16816(o[i][2 * dp + 1], ph, vh[dp][2], vh[dp][3]);
                    mma16816(o[i][2 * dp + 1], pl, vh[dp][2], vh[dp][3]);
                }
            }
        }

        __syncthreads();
        if (kt + 2 <= ktmax) load_kv(kt + 2, s);
        cpa_commit();
    }

    // ---- epilogue: O/l -> fp16 hi/lo for the O-proj GEMM ----
#pragma unroll
    for (int i = 0; i < 2; i++)
#pragma unroll
        for (int hf = 0; hf < 2; hf++) {
            const float inv = 1.0f / li[i][hf];
            const size_t row = (size_t)b * SQ + qt * 128 + warp * 32 + i * 16 + g + hf * 8;
#pragma unroll
            for (int j = 0; j < 8; j++) {
                const float x0 = o[i][j][hf * 2 + 0] * inv;
                const float x1 = o[i][j][hf * 2 + 1] * inv;
                const size_t idx = row * DM + h * DH + j * 8 + t2;
                const __half h0 = __float2half_rn(x0);
                const __half h1 = __float2half_rn(x1);
                *(uint32_t*)&g_ahi[idx] =
                    ((uint32_t)__half_as_ushort(h1) << 16) | __half_as_ushort(h0);
                *(uint32_t*)&g_alo[idx] =
                    packh(x0 - __half2float(h0), x1 - __half2float(h1));
            }
        }
}

// ---------------------------------------------------------------------------
extern "C" void kernel_launch(void* const* d_in, const int* in_sizes, int n_in,
                              void* d_out, int out_size)
{
    const float* x  = (const float*)d_in[0];
    const float* Qw = (const float*)d_in[1];
    const float* Qb = (const float*)d_in[2];
    const float* Kw = (const float*)d_in[3];
    const float* Kb = (const float*)d_in[4];
    const float* Vw = (const float*)d_in[5];
    const float* Vb = (const float*)d_in[6];
    const float* Ow = (const float*)d_in[7];
    const float* Ob = (const float*)d_in[8];
    float* out = (float*)d_out;

    cudaFuncSetAttribute(qkv_gemm, cudaFuncAttributeMaxDynamicSharedMemorySize, G_SMEM);
    cudaFuncSetAttribute(o_gemm,   cudaFuncAttributeMaxDynamicSharedMemorySize, G_SMEM);
    cudaFuncSetAttribute(attn_kernel, cudaFuncAttributeMaxDynamicSharedMemorySize, ATTN_SMEM);

    __half *xhi, *xlo, *ahi, *alo;
    cudaGetSymbolAddress((void**)&xhi, g_xhi);
    cudaGetSymbolAddress((void**)&xlo, g_xlo);
    cudaGetSymbolAddress((void**)&ahi, g_ahi);
    cudaGetSymbolAddress((void**)&alo, g_alo);

    cvt_split<<<ROWS * DM / 1024, 256>>>(x, xhi, xlo);
    cvt_wqkv<<<3 * DM * DM / 256, 256>>>(Qw, Kw, Vw);

    qkv_gemm<<<dim3(3 * DM / 128, ROWS / 128), 256, G_SMEM>>>(xhi, xlo, Qb, Kb, Vb);

    attn_kernel<<<dim3(SQ / 128, NH, BT), 128, ATTN_SMEM>>>();

    cvt_wo<<<DM * DM / 256, 256>>>(Ow);
    o_gemm<<<dim3(DM / 128, ROWS / 128), 256, G_SMEM>>>(ahi, alo, Ob, out);
}